// round 3
// baseline (speedup 1.0000x reference)
#include <cuda_runtime.h>
#include <cuda_fp16.h>

// ---------------------------------------------------------------------------
// Hetero-GNN (5 hetero_conv layers) over N=100000 nodes.
// R3: linearity trick (aggregate raw features, transform after) + fp16 gather.
//   per layer: agg_raw(h) -> aggT (temp sum), aggM (inter mean)
//              combine: h' = relu(aggT@Wt + aggM@Wi + h@Wr + b) [+ residual]
// ---------------------------------------------------------------------------

#define N_NODES 100000

// Scratch (device globals; no allocation allowed)
__device__ float  g_h   [N_NODES * 32];
__device__ float  g_h2  [N_NODES * 32];
__device__ __half g_hh  [N_NODES * 32];   // fp16 mirror of current h (gather src)
__device__ float  g_aggT[N_NODES * 32];   // temp-relation sum agg (head: stride 8)
__device__ float  g_aggM[N_NODES * 32];   // inter-relation mean agg

__device__ int g_deg_t[N_NODES];
__device__ int g_deg_i[N_NODES];
__device__ int g_rpt  [N_NODES + 1];
__device__ int g_rpi  [N_NODES + 1];
__device__ int g_bsum_t[1024];
__device__ int g_bsum_i[1024];
__device__ int g_col_t[100000];
__device__ int g_col_i[3200000];

// ---------------------------------------------------------------------------
// CSR build
// ---------------------------------------------------------------------------
__global__ void zero2_kernel(int* __restrict__ a, int* __restrict__ b, int n) {
    int i = blockIdx.x * blockDim.x + threadIdx.x;
    if (i < n) { a[i] = 0; b[i] = 0; }
}

__global__ void count_kernel(const int* __restrict__ dst, int E, int* __restrict__ deg) {
    int i = blockIdx.x * blockDim.x + threadIdx.x;
    if (i < E) atomicAdd(&deg[dst[i]], 1);
}

__global__ void scan_p1(const int* __restrict__ deg, int* __restrict__ rowptr,
                        int* __restrict__ bsum, int n) {
    __shared__ int sh[1024];
    int i = blockIdx.x * 1024 + threadIdx.x;
    int v = (i < n) ? deg[i] : 0;
    sh[threadIdx.x] = v;
    __syncthreads();
    for (int off = 1; off < 1024; off <<= 1) {
        int t = (threadIdx.x >= off) ? sh[threadIdx.x - off] : 0;
        __syncthreads();
        sh[threadIdx.x] += t;
        __syncthreads();
    }
    if (i < n) rowptr[i] = sh[threadIdx.x] - v;
    if (threadIdx.x == 1023) bsum[blockIdx.x] = sh[1023];
}

__global__ void scan_p2(int* __restrict__ bsum, int nb) {
    __shared__ int sh[1024];
    int v = (threadIdx.x < nb) ? bsum[threadIdx.x] : 0;
    sh[threadIdx.x] = v;
    __syncthreads();
    for (int off = 1; off < 1024; off <<= 1) {
        int t = (threadIdx.x >= off) ? sh[threadIdx.x - off] : 0;
        __syncthreads();
        sh[threadIdx.x] += t;
        __syncthreads();
    }
    if (threadIdx.x < nb) bsum[threadIdx.x] = sh[threadIdx.x] - v;
}

__global__ void scan_p3(int* __restrict__ rowptr, const int* __restrict__ bsum,
                        int* __restrict__ cursor, int n, int E) {
    int i = blockIdx.x * blockDim.x + threadIdx.x;
    if (i < n) {
        int v = rowptr[i] + bsum[i >> 10];
        rowptr[i] = v;
        cursor[i] = v;
    }
    if (i == 0) rowptr[n] = E;
}

__global__ void fill_kernel(const int* __restrict__ src, const int* __restrict__ dst,
                            int E, int* __restrict__ cursor, int* __restrict__ col) {
    int i = blockIdx.x * blockDim.x + threadIdx.x;
    if (i < E) {
        int d = dst[i];
        int p = atomicAdd(&cursor[d], 1);
        col[p] = src[i];
    }
}

// ---------------------------------------------------------------------------
// Head aggregation: gather raw x (6 ch, fp32) over both relations.
//   aggT (stride 8): sum over temp edges; aggM (stride 8): mean over inter.
// warp per node; lanes 0-5 carry channels.
// ---------------------------------------------------------------------------
__global__ void agg_head(const float* __restrict__ x,
                         const int* __restrict__ rpt, const int* __restrict__ colt,
                         const int* __restrict__ rpi, const int* __restrict__ coli,
                         float* __restrict__ aggT, float* __restrict__ aggM, int n) {
    int node = blockIdx.x * (blockDim.x >> 5) + (threadIdx.x >> 5);
    if (node >= n) return;
    int lane = threadIdx.x & 31;

    float at = 0.f, am = 0.f;

    int b0 = rpt[node], e0 = rpt[node + 1];
    for (int e = b0; e < e0; e++) {
        int s = colt[e];
        if (lane < 6) at += x[s * 6 + lane];
    }

    int b1 = rpi[node], e1 = rpi[node + 1];
    int e = b1;
    for (; e + 32 <= e1; e += 32) {
        int idx = coli[e + lane];
#pragma unroll
        for (int k = 0; k < 32; k++) {
            int s = __shfl_sync(0xffffffffu, idx, k);
            if (lane < 6) am += x[s * 6 + lane];
        }
    }
    if (e < e1) {
        int rem = e1 - e;
        int idx = (lane < rem) ? coli[e + lane] : 0;
        for (int k = 0; k < rem; k++) {
            int s = __shfl_sync(0xffffffffu, idx, k);
            if (lane < 6) am += x[s * 6 + lane];
        }
    }

    float invd = 1.0f / fmaxf((float)(e1 - b1), 1.0f);
    if (lane < 6) {
        aggT[node * 8 + lane] = at;
        aggM[node * 8 + lane] = am * invd;
    }
}

// ---------------------------------------------------------------------------
// Hidden aggregation: gather fp16 h (32 ch) over both relations.
// warp per node; paired edges: lanes 0-15 -> edge k, lanes 16-31 -> edge k+1;
// each lane loads __half2 (channels 2l, 2l+1). shfl_xor(16) merges halves.
// ---------------------------------------------------------------------------
__global__ void agg_hidden(const __half* __restrict__ hh,
                           const int* __restrict__ rpt, const int* __restrict__ colt,
                           const int* __restrict__ rpi, const int* __restrict__ coli,
                           float* __restrict__ aggT, float* __restrict__ aggM, int n) {
    int node = blockIdx.x * (blockDim.x >> 5) + (threadIdx.x >> 5);
    if (node >= n) return;
    int lane = threadIdx.x & 31;
    int half_id = lane >> 4;
    int l = lane & 15;

    const __half2* hh2 = (const __half2*)hh;

    float2 sT = make_float2(0.f, 0.f);
    float2 sM = make_float2(0.f, 0.f);

    // temp relation (sum), deg ~1: half-warp 0 loads
    int b0 = rpt[node], e0 = rpt[node + 1];
    for (int e = b0; e < e0; e++) {
        int s = colt[e];
        if (half_id == 0) {
            float2 f = __half22float2(hh2[s * 16 + l]);
            sT.x += f.x; sT.y += f.y;
        }
    }

    // inter relation (mean), paired edges
    int b1 = rpi[node], e1 = rpi[node + 1];
    int e = b1;
    for (; e + 32 <= e1; e += 32) {
        int idx = coli[e + lane];
#pragma unroll
        for (int k = 0; k < 32; k += 2) {
            int s = __shfl_sync(0xffffffffu, idx, k + half_id);
            float2 f = __half22float2(hh2[s * 16 + l]);
            sM.x += f.x; sM.y += f.y;
        }
    }
    if (e < e1) {
        int rem = e1 - e;
        int idx = (lane < rem) ? coli[e + lane] : 0;
        int kpair = rem & ~1;
        for (int k = 0; k < kpair; k += 2) {
            int s = __shfl_sync(0xffffffffu, idx, k + half_id);
            float2 f = __half22float2(hh2[s * 16 + l]);
            sM.x += f.x; sM.y += f.y;
        }
        if (rem & 1) {
            int s = __shfl_sync(0xffffffffu, idx, rem - 1);
            if (half_id == 0) {
                float2 f = __half22float2(hh2[s * 16 + l]);
                sM.x += f.x; sM.y += f.y;
            }
        }
    }

    // merge halves
    sM.x += __shfl_xor_sync(0xffffffffu, sM.x, 16);
    sM.y += __shfl_xor_sync(0xffffffffu, sM.y, 16);

    if (half_id == 0) {
        float invd = 1.0f / fmaxf((float)(e1 - b1), 1.0f);
        ((float2*)aggT)[node * 16 + l] = sT;
        float2 m = make_float2(sM.x * invd, sM.y * invd);
        ((float2*)aggM)[node * 16 + l] = m;
    }
}

// ---------------------------------------------------------------------------
// Head combine: h = relu(aggT@Wt + aggM@Wi + x@Wr + b)   (6 -> 32)
// warp per node, lane = out channel. Writes fp32 h + fp16 mirror.
// ---------------------------------------------------------------------------
__global__ void combine_head(const float* __restrict__ x,
                             const float* __restrict__ aggT, const float* __restrict__ aggM,
                             const float* __restrict__ Wt, const float* __restrict__ Wi,
                             const float* __restrict__ Wr, const float* __restrict__ b,
                             float* __restrict__ hout, __half* __restrict__ hh, int n) {
    __shared__ float sWt[6 * 32], sWi[6 * 32], sWr[6 * 32], sB[32];
    for (int i = threadIdx.x; i < 6 * 32; i += blockDim.x) {
        sWt[i] = Wt[i]; sWi[i] = Wi[i]; sWr[i] = Wr[i];
    }
    if (threadIdx.x < 32) sB[threadIdx.x] = b[threadIdx.x];
    __syncthreads();

    int node = blockIdx.x * (blockDim.x >> 5) + (threadIdx.x >> 5);
    if (node >= n) return;
    int lane = threadIdx.x & 31;

    float aT = (lane < 6) ? aggT[node * 8 + lane] : 0.f;
    float aM = (lane < 6) ? aggM[node * 8 + lane] : 0.f;
    float xv = (lane < 6) ? x[node * 6 + lane] : 0.f;

    float acc = sB[lane];
#pragma unroll
    for (int ci = 0; ci < 6; ci++) {
        float t = __shfl_sync(0xffffffffu, aT, ci);
        float m = __shfl_sync(0xffffffffu, aM, ci);
        float r = __shfl_sync(0xffffffffu, xv, ci);
        acc += t * sWt[ci * 32 + lane] + m * sWi[ci * 32 + lane] + r * sWr[ci * 32 + lane];
    }
    acc = fmaxf(acc, 0.f);
    hout[node * 32 + lane] = acc;
    hh[node * 32 + lane] = __float2half(acc);
}

// ---------------------------------------------------------------------------
// Hidden combine: h' = relu(aggT@Wt + aggM@Wi + h@Wr + b) + h   (32 -> 32)
// ---------------------------------------------------------------------------
__global__ void combine_hidden(const float* __restrict__ h,
                               const float* __restrict__ aggT, const float* __restrict__ aggM,
                               const float* __restrict__ Wt, const float* __restrict__ Wi,
                               const float* __restrict__ Wr, const float* __restrict__ b,
                               float* __restrict__ hout, __half* __restrict__ hh, int n) {
    __shared__ float sWt[32 * 32], sWi[32 * 32], sWr[32 * 32], sB[32];
    for (int i = threadIdx.x; i < 32 * 32; i += blockDim.x) {
        sWt[i] = Wt[i]; sWi[i] = Wi[i]; sWr[i] = Wr[i];
    }
    if (threadIdx.x < 32) sB[threadIdx.x] = b[threadIdx.x];
    __syncthreads();

    int node = blockIdx.x * (blockDim.x >> 5) + (threadIdx.x >> 5);
    if (node >= n) return;
    int lane = threadIdx.x & 31;

    float aT = aggT[node * 32 + lane];
    float aM = aggM[node * 32 + lane];
    float hv = h[node * 32 + lane];

    float acc = sB[lane];
#pragma unroll
    for (int ci = 0; ci < 32; ci++) {
        float t = __shfl_sync(0xffffffffu, aT, ci);
        float m = __shfl_sync(0xffffffffu, aM, ci);
        float r = __shfl_sync(0xffffffffu, hv, ci);
        acc += t * sWt[ci * 32 + lane] + m * sWi[ci * 32 + lane] + r * sWr[ci * 32 + lane];
    }
    acc = fmaxf(acc, 0.f) + hv;           // residual
    hout[node * 32 + lane] = acc;
    hh[node * 32 + lane] = __float2half(acc);
}

// ---------------------------------------------------------------------------
// Last combine: out = relu(aggT@Wt + aggM@Wi + h@Wr + b) + h@proj   (32 -> 64)
// lane handles out channels {lane, lane+32}.
// ---------------------------------------------------------------------------
__global__ void combine_last(const float* __restrict__ h,
                             const float* __restrict__ aggT, const float* __restrict__ aggM,
                             const float* __restrict__ Wt, const float* __restrict__ Wi,
                             const float* __restrict__ Wr, const float* __restrict__ b,
                             const float* __restrict__ Wp,
                             float* __restrict__ out, int n) {
    __shared__ float sWt[32 * 64], sWi[32 * 64], sWr[32 * 64], sWp[32 * 64], sB[64];
    for (int i = threadIdx.x; i < 32 * 64; i += blockDim.x) {
        sWt[i] = Wt[i]; sWi[i] = Wi[i]; sWr[i] = Wr[i]; sWp[i] = Wp[i];
    }
    if (threadIdx.x < 64) sB[threadIdx.x] = b[threadIdx.x];
    __syncthreads();

    int node = blockIdx.x * (blockDim.x >> 5) + (threadIdx.x >> 5);
    if (node >= n) return;
    int lane = threadIdx.x & 31;

    float aT = aggT[node * 32 + lane];
    float aM = aggM[node * 32 + lane];
    float hv = h[node * 32 + lane];

    float acc0 = sB[lane], acc1 = sB[lane + 32];
    float p0 = 0.f, p1 = 0.f;
#pragma unroll
    for (int ci = 0; ci < 32; ci++) {
        float t = __shfl_sync(0xffffffffu, aT, ci);
        float m = __shfl_sync(0xffffffffu, aM, ci);
        float r = __shfl_sync(0xffffffffu, hv, ci);
        acc0 += t * sWt[ci * 64 + lane]      + m * sWi[ci * 64 + lane]      + r * sWr[ci * 64 + lane];
        acc1 += t * sWt[ci * 64 + lane + 32] + m * sWi[ci * 64 + lane + 32] + r * sWr[ci * 64 + lane + 32];
        p0   += r * sWp[ci * 64 + lane];
        p1   += r * sWp[ci * 64 + lane + 32];
    }
    out[node * 64 + lane]      = fmaxf(acc0, 0.f) + p0;
    out[node * 64 + lane + 32] = fmaxf(acc1, 0.f) + p1;
}

// ---------------------------------------------------------------------------
// Launch
// ---------------------------------------------------------------------------
extern "C" void kernel_launch(void* const* d_in, const int* in_sizes, int n_in,
                              void* d_out, int out_size) {
    const float* x        = (const float*)d_in[0];
    const int*   ei_t     = (const int*)d_in[1];
    const int*   ei_i     = (const int*)d_in[2];
    const float* head_Wt  = (const float*)d_in[3];
    const float* head_Wi  = (const float*)d_in[4];
    const float* head_Wr  = (const float*)d_in[5];
    const float* head_b   = (const float*)d_in[6];
    const float* blk_Wt   = (const float*)d_in[7];
    const float* blk_Wi   = (const float*)d_in[8];
    const float* blk_Wr   = (const float*)d_in[9];
    const float* blk_b    = (const float*)d_in[10];
    const float* last_Wt  = (const float*)d_in[11];
    const float* last_Wi  = (const float*)d_in[12];
    const float* last_Wr  = (const float*)d_in[13];
    const float* last_b   = (const float*)d_in[14];
    const float* last_proj= (const float*)d_in[15];

    const int n  = in_sizes[0] / 6;      // 100000
    const int Et = in_sizes[1] / 2;      // 100000
    const int Ei = in_sizes[2] / 2;      // 3200000

    float *h, *h2, *aggT, *aggM;
    __half* hh;
    int *degt, *degi, *rpt, *rpi, *colt, *coli, *bst, *bsi;
    cudaGetSymbolAddress((void**)&h,    g_h);
    cudaGetSymbolAddress((void**)&h2,   g_h2);
    cudaGetSymbolAddress((void**)&hh,   g_hh);
    cudaGetSymbolAddress((void**)&aggT, g_aggT);
    cudaGetSymbolAddress((void**)&aggM, g_aggM);
    cudaGetSymbolAddress((void**)&degt, g_deg_t);
    cudaGetSymbolAddress((void**)&degi, g_deg_i);
    cudaGetSymbolAddress((void**)&rpt,  g_rpt);
    cudaGetSymbolAddress((void**)&rpi,  g_rpi);
    cudaGetSymbolAddress((void**)&bst,  g_bsum_t);
    cudaGetSymbolAddress((void**)&bsi,  g_bsum_i);
    cudaGetSymbolAddress((void**)&colt, g_col_t);
    cudaGetSymbolAddress((void**)&coli, g_col_i);

    const int T = 256;
    int nodeBlocks = (n * 32 + T - 1) / T;
    int nb = (n + 1023) / 1024;

    // --- CSR build ---
    zero2_kernel<<<(n + T - 1) / T, T>>>(degt, degi, n);
    count_kernel<<<(Et + T - 1) / T, T>>>(ei_t + Et, Et, degt);
    count_kernel<<<(Ei + T - 1) / T, T>>>(ei_i + Ei, Ei, degi);
    scan_p1<<<nb, 1024>>>(degt, rpt, bst, n);
    scan_p1<<<nb, 1024>>>(degi, rpi, bsi, n);
    scan_p2<<<1, 1024>>>(bst, nb);
    scan_p2<<<1, 1024>>>(bsi, nb);
    scan_p3<<<(n + T) / T, T>>>(rpt, bst, degt, n, Et);
    scan_p3<<<(n + T) / T, T>>>(rpi, bsi, degi, n, Ei);
    fill_kernel<<<(Et + T - 1) / T, T>>>(ei_t, ei_t + Et, Et, degt, colt);
    fill_kernel<<<(Ei + T - 1) / T, T>>>(ei_i, ei_i + Ei, Ei, degi, coli);

    // --- head: 6 -> 32 ---
    agg_head<<<nodeBlocks, T>>>(x, rpt, colt, rpi, coli, aggT, aggM, n);
    combine_head<<<nodeBlocks, T>>>(x, aggT, aggM, head_Wt, head_Wi, head_Wr,
                                    head_b, h, hh, n);

    // --- 3 residual blocks: 32 -> 32 ---
    for (int i = 0; i < 3; i++) {
        agg_hidden<<<nodeBlocks, T>>>(hh, rpt, colt, rpi, coli, aggT, aggM, n);
        combine_hidden<<<nodeBlocks, T>>>(h, aggT, aggM,
                                          blk_Wt + i * 32 * 32, blk_Wi + i * 32 * 32,
                                          blk_Wr + i * 32 * 32, blk_b + i * 32,
                                          h2, hh, n);
        float* tmp = h; h = h2; h2 = tmp;
    }

    // --- last: 32 -> 64 ---
    agg_hidden<<<nodeBlocks, T>>>(hh, rpt, colt, rpi, coli, aggT, aggM, n);
    combine_last<<<nodeBlocks, T>>>(h, aggT, aggM, last_Wt, last_Wi, last_Wr,
                                    last_b, last_proj, (float*)d_out, n);
}

// round 4
// speedup vs baseline: 1.1323x; 1.1323x over previous
#include <cuda_runtime.h>
#include <cuda_fp16.h>

// ---------------------------------------------------------------------------
// Hetero-GNN (5 hetero_conv layers) over N=100000 nodes.
// R4 = R2 structure (transform-then-gather CSR) with fp16 xt/xi gather arrays.
// Gather keeps warp-per-node, lane=channel, one contiguous row per edge.
// ---------------------------------------------------------------------------

#define N_NODES 100000
#define MAXC 64

// Scratch (device globals; no allocation allowed)
__device__ __half g_xt16[N_NODES * MAXC];   // transformed 'temp' messages (fp16)
__device__ __half g_xi16[N_NODES * MAXC];   // transformed 'inter' messages (fp16)
__device__ float  g_base[N_NODES * MAXC];   // x@Wr + b (fp32)
__device__ float  g_proj[N_NODES * MAXC];   // h@last_proj (fp32)
__device__ float  g_h   [N_NODES * 32];
__device__ float  g_h2  [N_NODES * 32];

__device__ int g_deg_t[N_NODES];
__device__ int g_deg_i[N_NODES];
__device__ int g_rpt  [N_NODES + 1];
__device__ int g_rpi  [N_NODES + 1];
__device__ int g_bsum_t[1024];
__device__ int g_bsum_i[1024];
__device__ int g_col_t[100000];
__device__ int g_col_i[3200000];

// ---------------------------------------------------------------------------
// CSR build (unchanged from R2)
// ---------------------------------------------------------------------------
__global__ void zero2_kernel(int* __restrict__ a, int* __restrict__ b, int n) {
    int i = blockIdx.x * blockDim.x + threadIdx.x;
    if (i < n) { a[i] = 0; b[i] = 0; }
}

__global__ void count_kernel(const int* __restrict__ dst, int E, int* __restrict__ deg) {
    int i = blockIdx.x * blockDim.x + threadIdx.x;
    if (i < E) atomicAdd(&deg[dst[i]], 1);
}

__global__ void scan_p1(const int* __restrict__ deg, int* __restrict__ rowptr,
                        int* __restrict__ bsum, int n) {
    __shared__ int sh[1024];
    int i = blockIdx.x * 1024 + threadIdx.x;
    int v = (i < n) ? deg[i] : 0;
    sh[threadIdx.x] = v;
    __syncthreads();
    for (int off = 1; off < 1024; off <<= 1) {
        int t = (threadIdx.x >= off) ? sh[threadIdx.x - off] : 0;
        __syncthreads();
        sh[threadIdx.x] += t;
        __syncthreads();
    }
    if (i < n) rowptr[i] = sh[threadIdx.x] - v;
    if (threadIdx.x == 1023) bsum[blockIdx.x] = sh[1023];
}

__global__ void scan_p2(int* __restrict__ bsum, int nb) {
    __shared__ int sh[1024];
    int v = (threadIdx.x < nb) ? bsum[threadIdx.x] : 0;
    sh[threadIdx.x] = v;
    __syncthreads();
    for (int off = 1; off < 1024; off <<= 1) {
        int t = (threadIdx.x >= off) ? sh[threadIdx.x - off] : 0;
        __syncthreads();
        sh[threadIdx.x] += t;
        __syncthreads();
    }
    if (threadIdx.x < nb) bsum[threadIdx.x] = sh[threadIdx.x] - v;
}

__global__ void scan_p3(int* __restrict__ rowptr, const int* __restrict__ bsum,
                        int* __restrict__ cursor, int n, int E) {
    int i = blockIdx.x * blockDim.x + threadIdx.x;
    if (i < n) {
        int v = rowptr[i] + bsum[i >> 10];
        rowptr[i] = v;
        cursor[i] = v;
    }
    if (i == 0) rowptr[n] = E;
}

__global__ void fill_kernel(const int* __restrict__ src, const int* __restrict__ dst,
                            int E, int* __restrict__ cursor, int* __restrict__ col) {
    int i = blockIdx.x * blockDim.x + threadIdx.x;
    if (i < E) {
        int d = dst[i];
        int p = atomicAdd(&cursor[d], 1);
        col[p] = src[i];
    }
}

// ---------------------------------------------------------------------------
// Transform: xt16 = fp16(x@Wt), xi16 = fp16(x@Wi), base = x@Wr + b [, proj]
// warp-per-node; lanes own output channels -> coalesced stores.
// ---------------------------------------------------------------------------
template<int CIN, int COUT, bool PROJ>
__global__ void transform_kernel(const float* __restrict__ x,
                                 const float* __restrict__ Wt,
                                 const float* __restrict__ Wi,
                                 const float* __restrict__ Wr,
                                 const float* __restrict__ b,
                                 const float* __restrict__ Wp,
                                 __half* __restrict__ xt16,
                                 __half* __restrict__ xi16,
                                 float* __restrict__ base,
                                 float* __restrict__ proj,
                                 int n) {
    __shared__ float sWt[CIN * COUT];
    __shared__ float sWi[CIN * COUT];
    __shared__ float sWr[CIN * COUT];
    __shared__ float sWp[PROJ ? (CIN * COUT) : 1];
    __shared__ float sB[COUT];
    for (int i = threadIdx.x; i < CIN * COUT; i += blockDim.x) {
        sWt[i] = Wt[i]; sWi[i] = Wi[i]; sWr[i] = Wr[i];
        if (PROJ) sWp[i] = Wp[i];
    }
    for (int i = threadIdx.x; i < COUT; i += blockDim.x) sB[i] = b[i];
    __syncthreads();

    int wpb  = blockDim.x >> 5;
    int node = blockIdx.x * wpb + (threadIdx.x >> 5);
    if (node >= n) return;
    int lane = threadIdx.x & 31;

    float xr[CIN];
#pragma unroll
    for (int ci = 0; ci < CIN; ci++) xr[ci] = x[node * CIN + ci];

    constexpr int R = (COUT + 31) / 32;
#pragma unroll
    for (int r = 0; r < R; r++) {
        int co = lane + 32 * r;
        float at = 0.f, ai = 0.f, ar = sB[co], ap = 0.f;
#pragma unroll
        for (int ci = 0; ci < CIN; ci++) {
            float xv = xr[ci];
            at = fmaf(xv, sWt[ci * COUT + co], at);
            ai = fmaf(xv, sWi[ci * COUT + co], ai);
            ar = fmaf(xv, sWr[ci * COUT + co], ar);
            if (PROJ) ap = fmaf(xv, sWp[ci * COUT + co], ap);
        }
        xt16[node * COUT + co] = __float2half(at);
        xi16[node * COUT + co] = __float2half(ai);
        base[node * COUT + co] = ar;
        if (PROJ) proj[node * COUT + co] = ap;
    }
}

// ---------------------------------------------------------------------------
// Aggregation, C=32. warp-per-node, lane = channel (fp16 load, fp32 acc).
// One contiguous 64B row per edge -> 1 wavefront/edge.
// MODE 0: out = relu(agg)            (head)
// MODE 1: out = relu(agg) + extra    (residual blocks, extra = h_prev)
// ---------------------------------------------------------------------------
template<int MODE>
__global__ void agg32_kernel(const __half* __restrict__ xt16, const __half* __restrict__ xi16,
                             const float* __restrict__ base,
                             const int* __restrict__ rpt, const int* __restrict__ colt,
                             const int* __restrict__ rpi, const int* __restrict__ coli,
                             const float* __restrict__ extra,
                             float* __restrict__ out, int n) {
    int node = blockIdx.x * (blockDim.x >> 5) + (threadIdx.x >> 5);
    if (node >= n) return;
    int lane = threadIdx.x & 31;

    float st = 0.f, si = 0.f;

    int b0 = rpt[node], e0 = rpt[node + 1];
    for (int e = b0; e < e0; e++) {
        int s = colt[e];
        st += __half2float(xt16[s * 32 + lane]);
    }

    int b1 = rpi[node], e1 = rpi[node + 1];
    int e = b1;
    for (; e + 32 <= e1; e += 32) {
        int idx = coli[e + lane];
#pragma unroll
        for (int k = 0; k < 32; k++) {
            int s = __shfl_sync(0xffffffffu, idx, k);
            si += __half2float(xi16[s * 32 + lane]);
        }
    }
    if (e < e1) {
        int rem = e1 - e;
        int idx = (lane < rem) ? coli[e + lane] : 0;
        for (int k = 0; k < rem; k++) {
            int s = __shfl_sync(0xffffffffu, idx, k);
            si += __half2float(xi16[s * 32 + lane]);
        }
    }

    float deg = (float)(e1 - b1);
    float v = st + si / fmaxf(deg, 1.0f) + base[node * 32 + lane];
    v = fmaxf(v, 0.0f);
    if (MODE == 1) v += extra[node * 32 + lane];
    out[node * 32 + lane] = v;
}

// ---------------------------------------------------------------------------
// Aggregation, C=64 (last layer). lane loads __half2 (channels 2l,2l+1):
// 32 lanes x 4B = 128B contiguous row -> 1 wavefront/edge.
// out = relu(agg) + extra  (extra = h @ last_proj)
// ---------------------------------------------------------------------------
__global__ void agg64_kernel(const __half* __restrict__ xt16, const __half* __restrict__ xi16,
                             const float* __restrict__ base,
                             const int* __restrict__ rpt, const int* __restrict__ colt,
                             const int* __restrict__ rpi, const int* __restrict__ coli,
                             const float* __restrict__ extra,
                             float* __restrict__ out, int n) {
    int node = blockIdx.x * (blockDim.x >> 5) + (threadIdx.x >> 5);
    if (node >= n) return;
    int lane = threadIdx.x & 31;

    const __half2* xt2 = (const __half2*)xt16;
    const __half2* xi2 = (const __half2*)xi16;

    float2 st = make_float2(0.f, 0.f), si = make_float2(0.f, 0.f);

    int b0 = rpt[node], e0 = rpt[node + 1];
    for (int e = b0; e < e0; e++) {
        int s = colt[e];
        float2 v = __half22float2(xt2[s * 32 + lane]);
        st.x += v.x; st.y += v.y;
    }

    int b1 = rpi[node], e1 = rpi[node + 1];
    int e = b1;
    for (; e + 32 <= e1; e += 32) {
        int idx = coli[e + lane];
#pragma unroll
        for (int k = 0; k < 32; k++) {
            int s = __shfl_sync(0xffffffffu, idx, k);
            float2 v = __half22float2(xi2[s * 32 + lane]);
            si.x += v.x; si.y += v.y;
        }
    }
    if (e < e1) {
        int rem = e1 - e;
        int idx = (lane < rem) ? coli[e + lane] : 0;
        for (int k = 0; k < rem; k++) {
            int s = __shfl_sync(0xffffffffu, idx, k);
            float2 v = __half22float2(xi2[s * 32 + lane]);
            si.x += v.x; si.y += v.y;
        }
    }

    float inv = 1.0f / fmaxf((float)(e1 - b1), 1.0f);
    float2 bs = ((const float2*)base)[node * 32 + lane];
    float2 ex = ((const float2*)extra)[node * 32 + lane];
    float2 r;
    r.x = fmaxf(st.x + si.x * inv + bs.x, 0.0f) + ex.x;
    r.y = fmaxf(st.y + si.y * inv + bs.y, 0.0f) + ex.y;
    ((float2*)out)[node * 32 + lane] = r;
}

// ---------------------------------------------------------------------------
// Launch
// ---------------------------------------------------------------------------
extern "C" void kernel_launch(void* const* d_in, const int* in_sizes, int n_in,
                              void* d_out, int out_size) {
    const float* x        = (const float*)d_in[0];
    const int*   ei_t     = (const int*)d_in[1];
    const int*   ei_i     = (const int*)d_in[2];
    const float* head_Wt  = (const float*)d_in[3];
    const float* head_Wi  = (const float*)d_in[4];
    const float* head_Wr  = (const float*)d_in[5];
    const float* head_b   = (const float*)d_in[6];
    const float* blk_Wt   = (const float*)d_in[7];
    const float* blk_Wi   = (const float*)d_in[8];
    const float* blk_Wr   = (const float*)d_in[9];
    const float* blk_b    = (const float*)d_in[10];
    const float* last_Wt  = (const float*)d_in[11];
    const float* last_Wi  = (const float*)d_in[12];
    const float* last_Wr  = (const float*)d_in[13];
    const float* last_b   = (const float*)d_in[14];
    const float* last_proj= (const float*)d_in[15];

    const int n  = in_sizes[0] / 6;      // 100000
    const int Et = in_sizes[1] / 2;      // 100000
    const int Ei = in_sizes[2] / 2;      // 3200000

    float *base, *proj, *h, *h2;
    __half *xt16, *xi16;
    int *degt, *degi, *rpt, *rpi, *colt, *coli, *bst, *bsi;
    cudaGetSymbolAddress((void**)&xt16, g_xt16);
    cudaGetSymbolAddress((void**)&xi16, g_xi16);
    cudaGetSymbolAddress((void**)&base, g_base);
    cudaGetSymbolAddress((void**)&proj, g_proj);
    cudaGetSymbolAddress((void**)&h,    g_h);
    cudaGetSymbolAddress((void**)&h2,   g_h2);
    cudaGetSymbolAddress((void**)&degt, g_deg_t);
    cudaGetSymbolAddress((void**)&degi, g_deg_i);
    cudaGetSymbolAddress((void**)&rpt,  g_rpt);
    cudaGetSymbolAddress((void**)&rpi,  g_rpi);
    cudaGetSymbolAddress((void**)&bst,  g_bsum_t);
    cudaGetSymbolAddress((void**)&bsi,  g_bsum_i);
    cudaGetSymbolAddress((void**)&colt, g_col_t);
    cudaGetSymbolAddress((void**)&coli, g_col_i);

    const int T = 256;
    int nodeBlocks = (n * 32 + T - 1) / T;
    int nb = (n + 1023) / 1024;

    // --- CSR build ---
    zero2_kernel<<<(n + T - 1) / T, T>>>(degt, degi, n);
    count_kernel<<<(Et + T - 1) / T, T>>>(ei_t + Et, Et, degt);
    count_kernel<<<(Ei + T - 1) / T, T>>>(ei_i + Ei, Ei, degi);
    scan_p1<<<nb, 1024>>>(degt, rpt, bst, n);
    scan_p1<<<nb, 1024>>>(degi, rpi, bsi, n);
    scan_p2<<<1, 1024>>>(bst, nb);
    scan_p2<<<1, 1024>>>(bsi, nb);
    scan_p3<<<(n + T) / T, T>>>(rpt, bst, degt, n, Et);
    scan_p3<<<(n + T) / T, T>>>(rpi, bsi, degi, n, Ei);
    fill_kernel<<<(Et + T - 1) / T, T>>>(ei_t, ei_t + Et, Et, degt, colt);
    fill_kernel<<<(Ei + T - 1) / T, T>>>(ei_i, ei_i + Ei, Ei, degi, coli);

    // --- head: 6 -> 32, relu ---
    transform_kernel<6, 32, false><<<nodeBlocks, T>>>(
        x, head_Wt, head_Wi, head_Wr, head_b, nullptr,
        xt16, xi16, base, nullptr, n);
    agg32_kernel<0><<<nodeBlocks, T>>>(xt16, xi16, base, rpt, colt, rpi, coli,
                                       nullptr, h, n);

    // --- 3 residual blocks: 32 -> 32, h = relu(conv(h)) + h ---
    for (int i = 0; i < 3; i++) {
        transform_kernel<32, 32, false><<<nodeBlocks, T>>>(
            h, blk_Wt + i * 32 * 32, blk_Wi + i * 32 * 32,
            blk_Wr + i * 32 * 32, blk_b + i * 32, nullptr,
            xt16, xi16, base, nullptr, n);
        agg32_kernel<1><<<nodeBlocks, T>>>(xt16, xi16, base, rpt, colt, rpi, coli,
                                           h, h2, n);
        float* tmp = h; h = h2; h2 = tmp;
    }

    // --- last: 32 -> 64, out = relu(conv(h)) + h @ last_proj ---
    transform_kernel<32, 64, true><<<nodeBlocks, T>>>(
        h, last_Wt, last_Wi, last_Wr, last_b, last_proj,
        xt16, xi16, base, proj, n);
    agg64_kernel<<<nodeBlocks, T>>>(xt16, xi16, base, rpt, colt, rpi, coli,
                                    proj, (float*)d_out, n);
}